// round 16
// baseline (speedup 1.0000x reference)
#include <cuda_runtime.h>
#include <math.h>

// ---------------------------------------------------------------------------
// Problem constants
// ---------------------------------------------------------------------------
#define T_DATA 20000
#define E_NO   1000
#define I_NO   200
#define T_NO   200
#define SUB    20
#define HN     10
#define COSN   20
#define NCHUNK (T_DATA / 32)     // 625
#define GEMM_BLOCKS 313          // ceil(20000/64)
#define PREP_BLOCKS 364          // ceil(93120/256)
#define ROOT_BLOCKS 157          // ceil(20000/128)
#define TRANS_BLOCKS 79          // ceil(20000/256)

#define OFF_V      0
#define OFF_CONVK  (T_DATA)                      // 20000
#define OFF_HIST   (OFF_CONVK + HN*SUB*2*T_NO)   // 100000
#define OFF_SPK    (OFF_HIST + SUB*T_NO)         // 104000
#define OFF_TH     (OFF_SPK + T_DATA*SUB)        // 504000

#define PI_F 3.14159274101257324f

// ---------------------------------------------------------------------------
// Device scratch (no allocations allowed)
// ---------------------------------------------------------------------------
__device__ float g_CK[SUB * T_NO * 2 * HN];       // [s][u][i*10+h]
__device__ float g_w[SUB * 256];                  // w[s][d]=hist_kern[s][200-d], d=1..200, else 0
__device__ float g_K[SUB * T_NO];                 // root alpha kernel (lag-indexed)
__device__ float g_SgT[2 * SUB * T_DATA];         // [channel][t]
__device__ float g_drive[SUB * T_DATA];           // [s][t]
__device__ float g_spk_sT[SUB * T_DATA];          // [s][t] spikes
__device__ float g_th_sT[SUB * T_DATA];           // [s][t] sub_thresh
__device__ int   g_prog[SUB];                     // scan progress (chunks done)

// ---------------------------------------------------------------------------
// Kernel 1: MERGED grouping GEMM + prep (R10 + g_prog zeroing).
// ---------------------------------------------------------------------------
__global__ void __launch_bounds__(256) gemmprep_kernel(
        const float* __restrict__ Se,
        const float* __restrict__ Si,
        const float* __restrict__ Ce,
        const float* __restrict__ Ci,
        const float* __restrict__ Wconv,
        const float* __restrict__ Whist,
        const float* __restrict__ Tau,
        const float* __restrict__ Wroot,
        float* __restrict__ out) {
    __shared__ float sS[64][33];
    __shared__ float sC[20][33];
    __shared__ float sBasis[COSN * T_NO];   // 16 KB (prep role)

    int tid = threadIdx.x;

    if (blockIdx.x >= GEMM_BLOCKS) {
        // ================= PREP role =================
        for (int i = tid; i < COSN * T_NO; i += 256) {
            int b = i / T_NO;
            int t = i % T_NO;
            float raw = 5.0f * logf((float)t + 1.0f);
            float phi = 1.57079632679f * (float)b;
            float d = raw - phi;
            float v = 0.0f;
            if (d >= -PI_F && d <= PI_F) v = 0.5f * cosf(d) + 0.5f;
            sBasis[i] = v;
        }
        __syncthreads();

        int idx = (blockIdx.x - GEMM_BLOCKS) * 256 + tid;
        if (idx < 80000) {
            int o = idx / 400;
            int i = (idx / 200) % 2;
            int u = idx % 200;
            float v = 0.0f;
            #pragma unroll
            for (int b = 0; b < COSN; b++)
                v = fmaf(Wconv[(o * 2 + i) * COSN + b], sBasis[b * T_NO + u], v);
            out[OFF_CONVK + o * 400 + i * 200 + (T_NO - 1 - u)] = v;
            int s = o / HN, h = o % HN;
            g_CK[s * (T_NO * 2 * HN) + u * (2 * HN) + i * HN + h] = v;
        } else if (idx < 84000) {
            int r = idx - 80000;
            int s = r / T_NO;
            int t = r % T_NO;
            float v = 0.0f;
            #pragma unroll
            for (int b = 0; b < COSN; b++)
                v = fmaf(Whist[s * COSN + b], sBasis[b * T_NO + t], v);
            out[OFF_HIST + r] = v;
        } else if (idx < 89120) {
            int r = idx - 84000;
            int s = r / 256;
            int d = r % 256;
            float v = 0.0f;
            if (d >= 1 && d <= T_NO) {
                int t = T_NO - d;
                #pragma unroll
                for (int b = 0; b < COSN; b++)
                    v = fmaf(Whist[s * COSN + b], sBasis[b * T_NO + t], v);
            }
            g_w[s * 256 + d] = v;
        } else if (idx < 93120) {
            int r = idx - 89120;
            int s = r / T_NO;
            int u = r % T_NO;
            float E = expf(Tau[s]);
            float x = (float)u / E;
            g_K[s * T_NO + u] = x * expf(-x) * expf(Wroot[s]);
        } else if (idx < 93120 + SUB) {
            g_prog[idx - 93120] = 0;
        }
        return;
    }

    // ================= GEMM role =================
    int t0 = blockIdx.x * 64;
    int row = tid >> 2;
    int g   = tid & 3;
    float acce[5] = {0.f, 0.f, 0.f, 0.f, 0.f};
    float acci[5] = {0.f, 0.f, 0.f, 0.f, 0.f};

    for (int k0 = 0; k0 < E_NO; k0 += 32) {
        #pragma unroll
        for (int r = 0; r < 8; r++) {
            int idx = tid + 256 * r;
            int rl = idx >> 5, cl = idx & 31;
            int gt = t0 + rl, gk = k0 + cl;
            sS[rl][cl] = (gt < T_DATA && gk < E_NO) ? Se[gt * E_NO + gk] : 0.f;
        }
        #pragma unroll
        for (int r = 0; r < 3; r++) {
            int idx = tid + 256 * r;
            if (idx < 640) {
                int sl = idx >> 5, cl = idx & 31;
                int gk = k0 + cl;
                sC[sl][cl] = (gk < E_NO) ? Ce[sl * E_NO + gk] : 0.f;
            }
        }
        __syncthreads();
        #pragma unroll
        for (int kk = 0; kk < 32; kk++) {
            float a = sS[row][kk];
            #pragma unroll
            for (int j = 0; j < 5; j++)
                acce[j] = fmaf(a, sC[g + 4 * j][kk], acce[j]);
        }
        __syncthreads();
    }
    for (int k0 = 0; k0 < I_NO; k0 += 32) {
        #pragma unroll
        for (int r = 0; r < 8; r++) {
            int idx = tid + 256 * r;
            int rl = idx >> 5, cl = idx & 31;
            int gt = t0 + rl, gk = k0 + cl;
            sS[rl][cl] = (gt < T_DATA && gk < I_NO) ? Si[gt * I_NO + gk] : 0.f;
        }
        #pragma unroll
        for (int r = 0; r < 3; r++) {
            int idx = tid + 256 * r;
            if (idx < 640) {
                int sl = idx >> 5, cl = idx & 31;
                int gk = k0 + cl;
                sC[sl][cl] = (gk < I_NO) ? Ci[sl * I_NO + gk] : 0.f;
            }
        }
        __syncthreads();
        #pragma unroll
        for (int kk = 0; kk < 32; kk++) {
            float a = sS[row][kk];
            #pragma unroll
            for (int j = 0; j < 5; j++)
                acci[j] = fmaf(a, sC[g + 4 * j][kk], acci[j]);
        }
        __syncthreads();
    }
    int gt = t0 + row;
    if (gt < T_DATA) {
        #pragma unroll
        for (int j = 0; j < 5; j++) {
            int s = g + 4 * j;
            g_SgT[(2 * s) * T_DATA + gt]     = acce[j];
            g_SgT[(2 * s + 1) * T_DATA + gt] = acci[j];
        }
    }
}

// ---------------------------------------------------------------------------
// Kernel 2: 200-tap causal conv + leaky + FF net -> drive[s][t] (unchanged).
// ---------------------------------------------------------------------------
__global__ void __launch_bounds__(128) conv_drive_kernel(
        const float* __restrict__ Wff,
        const float* __restrict__ Wff2,
        const float* __restrict__ thr) {
    int s  = blockIdx.y;
    int t0 = blockIdx.x * 512;
    int lt = threadIdx.x;

    __shared__ float sCK[T_NO * 2 * HN];   // 4000 floats
    __shared__ float sSe[712], sSi[712];
    __shared__ float sW[100], sW2[10];
    __shared__ float sth;

    for (int i = lt; i < 4000; i += 128)
        sCK[i] = g_CK[s * 4000 + i];
    for (int m = lt; m < 711; m += 128) {
        int gt = t0 - 199 + m;
        float ve = 0.f, vi = 0.f;
        if (gt >= 0 && gt < T_DATA) {
            ve = g_SgT[(2 * s) * T_DATA + gt];
            vi = g_SgT[(2 * s + 1) * T_DATA + gt];
        }
        sSe[m] = ve; sSi[m] = vi;
    }
    if (lt < 100) sW[lt]  = Wff[s * 100 + lt];
    if (lt < 10)  sW2[lt] = Wff2[s * 10 + lt];
    if (lt == 0)  sth = thr[s];
    __syncthreads();

    float acc[4][10];
    #pragma unroll
    for (int q = 0; q < 4; q++)
        #pragma unroll
        for (int h = 0; h < 10; h++) acc[q][h] = 0.f;

    for (int u = 0; u < T_NO; u++) {
        float se[4], si[4];
        #pragma unroll
        for (int q = 0; q < 4; q++) {
            se[q] = sSe[lt + 128 * q + 199 - u];
            si[q] = sSi[lt + 128 * q + 199 - u];
        }
        const float4* c4 = reinterpret_cast<const float4*>(sCK + u * 20);
        float4 a0 = c4[0], a1 = c4[1], a2 = c4[2], a3 = c4[3], a4 = c4[4];
        #pragma unroll
        for (int q = 0; q < 4; q++) {
            acc[q][0] = fmaf(a0.x, se[q], fmaf(a2.z, si[q], acc[q][0]));
            acc[q][1] = fmaf(a0.y, se[q], fmaf(a2.w, si[q], acc[q][1]));
            acc[q][2] = fmaf(a0.z, se[q], fmaf(a3.x, si[q], acc[q][2]));
            acc[q][3] = fmaf(a0.w, se[q], fmaf(a3.y, si[q], acc[q][3]));
            acc[q][4] = fmaf(a1.x, se[q], fmaf(a3.z, si[q], acc[q][4]));
            acc[q][5] = fmaf(a1.y, se[q], fmaf(a3.w, si[q], acc[q][5]));
            acc[q][6] = fmaf(a1.z, se[q], fmaf(a4.x, si[q], acc[q][6]));
            acc[q][7] = fmaf(a1.w, se[q], fmaf(a4.y, si[q], acc[q][7]));
            acc[q][8] = fmaf(a2.x, se[q], fmaf(a4.z, si[q], acc[q][8]));
            acc[q][9] = fmaf(a2.y, se[q], fmaf(a4.w, si[q], acc[q][9]));
        }
    }

    #pragma unroll
    for (int q = 0; q < 4; q++) {
        int t = t0 + lt + 128 * q;
        if (t >= T_DATA) continue;
        float co[10];
        #pragma unroll
        for (int h = 0; h < 10; h++) {
            float a = acc[q][h];
            co[h] = a > 0.f ? a : 0.01f * a;
        }
        float dsum = 0.f;
        #pragma unroll
        for (int k = 0; k < 10; k++) {
            float v = 0.f;
            #pragma unroll
            for (int h = 0; h < 10; h++)
                v = fmaf(co[h], sW[h * 10 + k], v);
            v = v > 0.f ? v : 0.01f * v;
            dsum = fmaf(v, sW2[k], dsum);
        }
        g_drive[s * T_DATA + t] = dsum + sth;
    }
}

// ---------------------------------------------------------------------------
// Kernel 3: FUSED scan + postprocess.
// Blocks 0..19: exact R10 scan (one subunit each) + progress publication
//   every 16 chunks (fence-all, syncwarp, lane0 store).
// Blocks 20..176: root conv (exact R10 body), waits on g_prog via nanosleep.
// Blocks 177..255: transpose (exact R10 body), waits on g_prog via nanosleep.
// ---------------------------------------------------------------------------
__device__ __forceinline__ void wait_progress(int need) {
    if (need > NCHUNK) need = NCHUNK;
    for (int s = 0; s < SUB; s++) {
        while (*(volatile int*)&g_prog[s] < need)
            __nanosleep(200);
    }
    __threadfence();
}

__global__ void __launch_bounds__(256, 1) scanpost_kernel(float* __restrict__ out) {
    __shared__ __align__(16) char buf[43200];
    __shared__ __align__(16) float ring[256];
    __shared__ __align__(16) float wext[256];
    __shared__ float baseB[2][2][32];

    int tid = threadIdx.x;
    int bid = blockIdx.x;

    if (bid >= SUB + ROOT_BLOCKS) {
        // ================= TRANSPOSE role =================
        int bx = bid - SUB - ROOT_BLOCKS;
        int t0 = bx * 256;
        if (tid == 0) wait_progress(t0 / 32 + 8);
        __syncthreads();

        float (*sh)[257] = reinterpret_cast<float (*)[257]>(buf);  // [SUB][257]
        #pragma unroll
        for (int half = 0; half < 2; half++) {
            const float* in = half ? g_th_sT : g_spk_sT;
            float* op = out + (half ? OFF_TH : OFF_SPK);
            int t = t0 + tid;
            if (t < T_DATA) {
                #pragma unroll
                for (int s = 0; s < SUB; s++)
                    sh[s][tid] = in[s * T_DATA + t];
            }
            __syncthreads();
            for (int i = tid; i < SUB * 256; i += 256) {
                int tl = i / SUB, s = i % SUB;
                int tt = t0 + tl;
                if (tt < T_DATA) op[tt * SUB + s] = sh[s][tl];
            }
            __syncthreads();
        }
        return;
    }

    if (bid >= SUB) {
        // ================= ROOT role =================
        int bx = bid - SUB;
        int t0 = bx * 128;
        if (tid == 0) wait_progress(t0 / 32 + 4);
        __syncthreads();

        float* sK   = reinterpret_cast<float*>(buf);             // 4000
        float* sSpk = reinterpret_cast<float*>(buf) + 4000;      // 20*328 = 6560

        for (int i = tid; i < SUB * T_NO; i += 256) sK[i] = g_K[i];
        for (int i = tid; i < SUB * 327; i += 256) {
            int s = i / 327;
            int m = i % 327;
            int gt = t0 - 200 + m;
            sSpk[s * 328 + m] = (gt >= 0 && gt < T_DATA) ? g_spk_sT[s * T_DATA + gt] : 0.f;
        }
        __syncthreads();

        if (tid >= 128) return;
        int lt = tid;
        int t = t0 + lt;
        if (t >= T_DATA) return;

        float acc0 = 0.f, acc1 = 0.f;
        for (int s = 0; s < SUB; s++) {
            const float* Ks = sK + s * T_NO;
            const float* Ss = sSpk + s * 328 + lt;
            #pragma unroll 4
            for (int u = 0; u < T_NO; u += 2) {
                acc0 = fmaf(Ks[u],     Ss[199 - u], acc0);
                acc1 = fmaf(Ks[u + 1], Ss[198 - u], acc1);
            }
        }
        out[OFF_V + t] = acc0 + acc1;
        return;
    }

    // ================= SCAN role (exact R10 + progress publish) =================
    if (tid >= 96) return;

    int s = bid;
    int wid = tid >> 5, lane = tid & 31;

    for (int i = tid; i < 256; i += 96) {
        ring[i] = 0.f;
        wext[i] = g_w[s * 256 + i];
    }
    __syncthreads();

    const float* dr = g_drive + s * T_DATA;
    float* osp = g_spk_sT + s * T_DATA;
    float* oth = g_th_sT + s * T_DATA;

    if (wid != 1) {
        int g = wid >> 1;                 // wid 0 -> 0, wid 2 -> 1
        int c4lo = 33 + g * 84;           // 33..113 / 117..197
        float drcur = (g == 0) ? dr[lane] : 0.f;
        for (int it = 0; it <= NCHUNK; it++) {
            if (it < NCHUNK) {
                int T = it * 32;
                float drnx = 0.f;
                if (g == 0 && it + 1 < NCHUNK) drnx = dr[(it + 1) * 32 + lane];
                float b0 = 0.f, b1 = 0.f, b2 = 0.f, b3 = 0.f;
                #pragma unroll
                for (int q = 0; q < 21; q++) {
                    int c4 = c4lo + 4 * q;
                    int p = (T - c4 - 3) & 255;
                    float4 r4 = *reinterpret_cast<const float4*>(ring + p);
                    b0 = fmaf(wext[c4 + lane],     r4.w, b0);
                    b1 = fmaf(wext[c4 + 1 + lane], r4.z, b1);
                    b2 = fmaf(wext[c4 + 2 + lane], r4.y, b2);
                    b3 = fmaf(wext[c4 + 3 + lane], r4.x, b3);
                }
                float sum = (b0 + b1) + (b2 + b3);
                if (g == 0) sum += drcur;
                baseB[it & 1][g][lane] = sum;
                drcur = drnx;
            }
            __syncthreads();
        }
    } else {
        float wregB[33];
        #pragma unroll
        for (int j = 1; j <= 32; j++) wregB[j] = g_w[s * 256 + lane + j];
        float wregU[32];
        #pragma unroll
        for (int k = 0; k < 32; k++) {
            int idx = lane - 31 + k;
            wregU[k] = (idx >= 1) ? g_w[s * 256 + idx] : 0.f;
        }
        float wr[8];
        #pragma unroll
        for (int j = 1; j < 8; j++) wr[j] = g_w[s * 256 + j];

        float spkAll[32];
        #pragma unroll
        for (int k = 0; k < 32; k++) spkAll[k] = 0.f;

        for (int it = 0; it <= NCHUNK; it++) {
            if (it >= 1) {
                int c = it - 1;
                int T = c * 32;
                float v = baseB[c & 1][0][lane] + baseB[c & 1][1][lane];
                float a0 = 0.f, a1 = 0.f, a2 = 0.f, a3 = 0.f;
                #pragma unroll
                for (int q = 0; q < 8; q++) {
                    a0 = fmaf(wregB[32 - 4 * q], spkAll[4 * q],     a0);
                    a1 = fmaf(wregB[31 - 4 * q], spkAll[4 * q + 1], a1);
                    a2 = fmaf(wregB[30 - 4 * q], spkAll[4 * q + 2], a2);
                    a3 = fmaf(wregB[29 - 4 * q], spkAll[4 * q + 3], a3);
                }
                v += (a0 + a1) + (a2 + a3);

                #pragma unroll
                for (int b = 0; b < 4; b++) {
                    float sv[8];
                    #pragma unroll
                    for (int i = 0; i < 8; i++)
                        sv[i] = __shfl_sync(0xffffffffu, v, 8 * b + i);
                    #pragma unroll
                    for (int i = 0; i < 8; i++) {
                        spkAll[8 * b + i] = sv[i] > 0.f ? 1.f : 0.f;
                        #pragma unroll
                        for (int j = i + 1; j < 8; j++)
                            sv[j] = fmaf(spkAll[8 * b + i], wr[j - i], sv[j]);
                    }
                    #pragma unroll
                    for (int i = 0; i < 8; i++)
                        v = fmaf(spkAll[8 * b + i], wregU[31 - 8 * b - i], v);
                }

                float myspk = v > 0.f ? 1.f : 0.f;
                ring[(T + lane) & 255] = myspk;
                oth[T + lane] = v;
                osp[T + lane] = myspk;

                // progress publication (every 16 chunks + final)
                int done = c + 1;
                if ((done & 15) == 0 || done == NCHUNK) {
                    __threadfence();
                    __syncwarp();
                    if (lane == 0)
                        *(volatile int*)&g_prog[s] = done;
                }
            }
            __syncthreads();
        }
    }
}

// ---------------------------------------------------------------------------
// Launch
// ---------------------------------------------------------------------------
extern "C" void kernel_launch(void* const* d_in, const int* in_sizes, int n_in,
                              void* d_out, int out_size) {
    const float* S_e    = (const float*)d_in[0];
    const float* S_i    = (const float*)d_in[1];
    const float* Csyn_e = (const float*)d_in[2];
    const float* Csyn_i = (const float*)d_in[3];
    const float* W_conv = (const float*)d_in[4];
    const float* thresh = (const float*)d_in[5];
    const float* W_ff   = (const float*)d_in[6];
    const float* W_ff2  = (const float*)d_in[7];
    const float* Tau    = (const float*)d_in[8];
    const float* W_root = (const float*)d_in[9];
    const float* W_hist = (const float*)d_in[10];
    float* out = (float*)d_out;

    (void)in_sizes; (void)n_in; (void)out_size;

    gemmprep_kernel<<<GEMM_BLOCKS + PREP_BLOCKS, 256>>>(
        S_e, S_i, Csyn_e, Csyn_i, W_conv, W_hist, Tau, W_root, out);
    {
        dim3 grid((T_DATA + 511) / 512, SUB);
        conv_drive_kernel<<<grid, 128>>>(W_ff, W_ff2, thresh);
    }
    scanpost_kernel<<<SUB + ROOT_BLOCKS + TRANS_BLOCKS, 256>>>(out);
}

// round 17
// speedup vs baseline: 1.1080x; 1.1080x over previous
#include <cuda_runtime.h>
#include <math.h>

// ---------------------------------------------------------------------------
// Problem constants
// ---------------------------------------------------------------------------
#define T_DATA 20000
#define E_NO   1000
#define I_NO   200
#define T_NO   200
#define SUB    20
#define HN     10
#define COSN   20
#define NCHUNK (T_DATA / 32)     // 625
#define GEMM_BLOCKS 157          // ceil(20000/128)
#define PREP_BLOCKS 364          // ceil(93120/256)

#define OFF_V      0
#define OFF_CONVK  (T_DATA)                      // 20000
#define OFF_HIST   (OFF_CONVK + HN*SUB*2*T_NO)   // 100000
#define OFF_SPK    (OFF_HIST + SUB*T_NO)         // 104000
#define OFF_TH     (OFF_SPK + T_DATA*SUB)        // 504000

#define PI_F 3.14159274101257324f

// GEMM tiling
#define TT   128                  // timesteps per block
#define KT   40                   // k per tile
#define SPAD 44                   // padded row stride (floats, 16B-aligned)

// ---------------------------------------------------------------------------
// Device scratch (no allocations allowed)
// ---------------------------------------------------------------------------
__device__ float g_CK[SUB * T_NO * 2 * HN];       // [s][u][i*10+h]
__device__ float g_w[SUB * 256];                  // w[s][d]=hist_kern[s][200-d], d=1..200, else 0
__device__ float g_K[SUB * T_NO];                 // root alpha kernel (lag-indexed)
__device__ float g_SgT[2 * SUB * T_DATA];         // [channel][t]
__device__ float g_drive[SUB * T_DATA];           // [s][t]
__device__ float g_spk_sT[SUB * T_DATA];          // [s][t] spikes
__device__ float g_th_sT[SUB * T_DATA];           // [s][t] sub_thresh

// ---------------------------------------------------------------------------
// Kernel 1: MERGED grouping GEMM (v2: float4 / 128x40 tiles) + prep.
// Accumulation order is strictly k-ascending per output -> bitwise identical
// to the previous version.
// ---------------------------------------------------------------------------
__global__ void __launch_bounds__(256) gemmprep_kernel(
        const float* __restrict__ Se,
        const float* __restrict__ Si,
        const float* __restrict__ Ce,
        const float* __restrict__ Ci,
        const float* __restrict__ Wconv,
        const float* __restrict__ Whist,
        const float* __restrict__ Tau,
        const float* __restrict__ Wroot,
        float* __restrict__ out) {
    __shared__ __align__(16) char gbuf[(TT * SPAD + SUB * SPAD) * 4]; // 26048 B
    float* sS = reinterpret_cast<float*>(gbuf);            // [TT][SPAD]
    float* sC = reinterpret_cast<float*>(gbuf) + TT * SPAD; // [SUB][SPAD]

    int tid = threadIdx.x;

    if (blockIdx.x >= GEMM_BLOCKS) {
        // ================= PREP role =================
        float* sBasis = reinterpret_cast<float*>(gbuf);    // 4000 floats
        for (int i = tid; i < COSN * T_NO; i += 256) {
            int b = i / T_NO;
            int t = i % T_NO;
            float raw = 5.0f * logf((float)t + 1.0f);
            float phi = 1.57079632679f * (float)b;
            float d = raw - phi;
            float v = 0.0f;
            if (d >= -PI_F && d <= PI_F) v = 0.5f * cosf(d) + 0.5f;
            sBasis[i] = v;
        }
        __syncthreads();

        int idx = (blockIdx.x - GEMM_BLOCKS) * 256 + tid;
        if (idx < 80000) {
            int o = idx / 400;
            int i = (idx / 200) % 2;
            int u = idx % 200;
            float v = 0.0f;
            #pragma unroll
            for (int b = 0; b < COSN; b++)
                v = fmaf(Wconv[(o * 2 + i) * COSN + b], sBasis[b * T_NO + u], v);
            out[OFF_CONVK + o * 400 + i * 200 + (T_NO - 1 - u)] = v;
            int s = o / HN, h = o % HN;
            g_CK[s * (T_NO * 2 * HN) + u * (2 * HN) + i * HN + h] = v;
        } else if (idx < 84000) {
            int r = idx - 80000;
            int s = r / T_NO;
            int t = r % T_NO;
            float v = 0.0f;
            #pragma unroll
            for (int b = 0; b < COSN; b++)
                v = fmaf(Whist[s * COSN + b], sBasis[b * T_NO + t], v);
            out[OFF_HIST + r] = v;
        } else if (idx < 89120) {
            int r = idx - 84000;
            int s = r / 256;
            int d = r % 256;
            float v = 0.0f;
            if (d >= 1 && d <= T_NO) {
                int t = T_NO - d;
                #pragma unroll
                for (int b = 0; b < COSN; b++)
                    v = fmaf(Whist[s * COSN + b], sBasis[b * T_NO + t], v);
            }
            g_w[s * 256 + d] = v;
        } else if (idx < 93120) {
            int r = idx - 89120;
            int s = r / T_NO;
            int u = r % T_NO;
            float E = expf(Tau[s]);
            float x = (float)u / E;
            g_K[s * T_NO + u] = x * expf(-x) * expf(Wroot[s]);
        }
        return;
    }

    // ================= GEMM role (v2) =================
    int t0 = blockIdx.x * TT;
    int row = tid >> 1;       // 0..127
    int g   = tid & 1;        // subunit half: s = g*10 + j

    float acce[10], acci[10];
    #pragma unroll
    for (int j = 0; j < 10; j++) { acce[j] = 0.f; acci[j] = 0.f; }

    const float4 z4 = make_float4(0.f, 0.f, 0.f, 0.f);

    // ---------- excitatory: K = 1000, 25 tiles of 40 ----------
    for (int k0 = 0; k0 < E_NO; k0 += KT) {
        #pragma unroll
        for (int r = 0; r < 5; r++) {
            int idx = tid + 256 * r;           // 0..1279
            int rl = idx / 10;
            int q  = idx % 10;
            int gt = t0 + rl;
            float4 v = (gt < T_DATA)
                ? *reinterpret_cast<const float4*>(Se + gt * E_NO + k0 + 4 * q)
                : z4;
            *reinterpret_cast<float4*>(sS + rl * SPAD + 4 * q) = v;
        }
        if (tid < 200) {
            int s = tid / 10, q = tid % 10;
            *reinterpret_cast<float4*>(sC + s * SPAD + 4 * q) =
                *reinterpret_cast<const float4*>(Ce + s * E_NO + k0 + 4 * q);
        }
        __syncthreads();

        #pragma unroll
        for (int q = 0; q < 10; q++) {
            float4 a4 = *reinterpret_cast<const float4*>(sS + row * SPAD + 4 * q);
            #pragma unroll
            for (int j = 0; j < 10; j++) {
                float4 c4 = *reinterpret_cast<const float4*>(sC + (g * 10 + j) * SPAD + 4 * q);
                acce[j] = fmaf(a4.x, c4.x, acce[j]);
                acce[j] = fmaf(a4.y, c4.y, acce[j]);
                acce[j] = fmaf(a4.z, c4.z, acce[j]);
                acce[j] = fmaf(a4.w, c4.w, acce[j]);
            }
        }
        __syncthreads();
    }

    // ---------- inhibitory: K = 200, 5 tiles of 40 ----------
    for (int k0 = 0; k0 < I_NO; k0 += KT) {
        #pragma unroll
        for (int r = 0; r < 5; r++) {
            int idx = tid + 256 * r;
            int rl = idx / 10;
            int q  = idx % 10;
            int gt = t0 + rl;
            float4 v = (gt < T_DATA)
                ? *reinterpret_cast<const float4*>(Si + gt * I_NO + k0 + 4 * q)
                : z4;
            *reinterpret_cast<float4*>(sS + rl * SPAD + 4 * q) = v;
        }
        if (tid < 200) {
            int s = tid / 10, q = tid % 10;
            *reinterpret_cast<float4*>(sC + s * SPAD + 4 * q) =
                *reinterpret_cast<const float4*>(Ci + s * I_NO + k0 + 4 * q);
        }
        __syncthreads();

        #pragma unroll
        for (int q = 0; q < 10; q++) {
            float4 a4 = *reinterpret_cast<const float4*>(sS + row * SPAD + 4 * q);
            #pragma unroll
            for (int j = 0; j < 10; j++) {
                float4 c4 = *reinterpret_cast<const float4*>(sC + (g * 10 + j) * SPAD + 4 * q);
                acci[j] = fmaf(a4.x, c4.x, acci[j]);
                acci[j] = fmaf(a4.y, c4.y, acci[j]);
                acci[j] = fmaf(a4.z, c4.z, acci[j]);
                acci[j] = fmaf(a4.w, c4.w, acci[j]);
            }
        }
        __syncthreads();
    }

    int gt = t0 + row;
    if (gt < T_DATA) {
        #pragma unroll
        for (int j = 0; j < 10; j++) {
            int s = g * 10 + j;
            g_SgT[(2 * s) * T_DATA + gt]     = acce[j];
            g_SgT[(2 * s + 1) * T_DATA + gt] = acci[j];
        }
    }
}

// ---------------------------------------------------------------------------
// Kernel 2: 200-tap causal conv + leaky + FF net -> drive[s][t] (unchanged).
// ---------------------------------------------------------------------------
__global__ void __launch_bounds__(128) conv_drive_kernel(
        const float* __restrict__ Wff,
        const float* __restrict__ Wff2,
        const float* __restrict__ thr) {
    int s  = blockIdx.y;
    int t0 = blockIdx.x * 512;
    int lt = threadIdx.x;

    __shared__ float sCK[T_NO * 2 * HN];   // 4000 floats
    __shared__ float sSe[712], sSi[712];
    __shared__ float sW[100], sW2[10];
    __shared__ float sth;

    for (int i = lt; i < 4000; i += 128)
        sCK[i] = g_CK[s * 4000 + i];
    for (int m = lt; m < 711; m += 128) {
        int gt = t0 - 199 + m;
        float ve = 0.f, vi = 0.f;
        if (gt >= 0 && gt < T_DATA) {
            ve = g_SgT[(2 * s) * T_DATA + gt];
            vi = g_SgT[(2 * s + 1) * T_DATA + gt];
        }
        sSe[m] = ve; sSi[m] = vi;
    }
    if (lt < 100) sW[lt]  = Wff[s * 100 + lt];
    if (lt < 10)  sW2[lt] = Wff2[s * 10 + lt];
    if (lt == 0)  sth = thr[s];
    __syncthreads();

    float acc[4][10];
    #pragma unroll
    for (int q = 0; q < 4; q++)
        #pragma unroll
        for (int h = 0; h < 10; h++) acc[q][h] = 0.f;

    for (int u = 0; u < T_NO; u++) {
        float se[4], si[4];
        #pragma unroll
        for (int q = 0; q < 4; q++) {
            se[q] = sSe[lt + 128 * q + 199 - u];
            si[q] = sSi[lt + 128 * q + 199 - u];
        }
        const float4* c4 = reinterpret_cast<const float4*>(sCK + u * 20);
        float4 a0 = c4[0], a1 = c4[1], a2 = c4[2], a3 = c4[3], a4 = c4[4];
        #pragma unroll
        for (int q = 0; q < 4; q++) {
            acc[q][0] = fmaf(a0.x, se[q], fmaf(a2.z, si[q], acc[q][0]));
            acc[q][1] = fmaf(a0.y, se[q], fmaf(a2.w, si[q], acc[q][1]));
            acc[q][2] = fmaf(a0.z, se[q], fmaf(a3.x, si[q], acc[q][2]));
            acc[q][3] = fmaf(a0.w, se[q], fmaf(a3.y, si[q], acc[q][3]));
            acc[q][4] = fmaf(a1.x, se[q], fmaf(a3.z, si[q], acc[q][4]));
            acc[q][5] = fmaf(a1.y, se[q], fmaf(a3.w, si[q], acc[q][5]));
            acc[q][6] = fmaf(a1.z, se[q], fmaf(a4.x, si[q], acc[q][6]));
            acc[q][7] = fmaf(a1.w, se[q], fmaf(a4.y, si[q], acc[q][7]));
            acc[q][8] = fmaf(a2.x, se[q], fmaf(a4.z, si[q], acc[q][8]));
            acc[q][9] = fmaf(a2.y, se[q], fmaf(a4.w, si[q], acc[q][9]));
        }
    }

    #pragma unroll
    for (int q = 0; q < 4; q++) {
        int t = t0 + lt + 128 * q;
        if (t >= T_DATA) continue;
        float co[10];
        #pragma unroll
        for (int h = 0; h < 10; h++) {
            float a = acc[q][h];
            co[h] = a > 0.f ? a : 0.01f * a;
        }
        float dsum = 0.f;
        #pragma unroll
        for (int k = 0; k < 10; k++) {
            float v = 0.f;
            #pragma unroll
            for (int h = 0; h < 10; h++)
                v = fmaf(co[h], sW[h * 10 + k], v);
            v = v > 0.f ? v : 0.01f * v;
            dsum = fmaf(v, sW2[k], dsum);
        }
        g_drive[s * T_DATA + t] = dsum + sth;
    }
}

// ---------------------------------------------------------------------------
// Kernel 3: pipelined spike scan — EXACT R10 version (FROZEN, known best).
// ---------------------------------------------------------------------------
__global__ void __launch_bounds__(96, 1) scan_kernel() {
    int s = blockIdx.x;
    int tid = threadIdx.x;
    int wid = tid >> 5, lane = tid & 31;

    __shared__ __align__(16) float ring[256];
    __shared__ __align__(16) float wext[256];
    __shared__ float baseB[2][2][32];

    for (int i = tid; i < 256; i += 96) {
        ring[i] = 0.f;
        wext[i] = g_w[s * 256 + i];
    }
    __syncthreads();

    const float* dr = g_drive + s * T_DATA;
    float* osp = g_spk_sT + s * T_DATA;
    float* oth = g_th_sT + s * T_DATA;

    if (wid != 1) {
        int g = wid >> 1;                 // wid 0 -> 0, wid 2 -> 1
        int c4lo = 33 + g * 84;           // 33..113 / 117..197
        float drcur = (g == 0) ? dr[lane] : 0.f;
        for (int it = 0; it <= NCHUNK; it++) {
            if (it < NCHUNK) {
                int T = it * 32;
                float drnx = 0.f;
                if (g == 0 && it + 1 < NCHUNK) drnx = dr[(it + 1) * 32 + lane];
                float b0 = 0.f, b1 = 0.f, b2 = 0.f, b3 = 0.f;
                #pragma unroll
                for (int q = 0; q < 21; q++) {
                    int c4 = c4lo + 4 * q;
                    int p = (T - c4 - 3) & 255;
                    float4 r4 = *reinterpret_cast<const float4*>(ring + p);
                    b0 = fmaf(wext[c4 + lane],     r4.w, b0);
                    b1 = fmaf(wext[c4 + 1 + lane], r4.z, b1);
                    b2 = fmaf(wext[c4 + 2 + lane], r4.y, b2);
                    b3 = fmaf(wext[c4 + 3 + lane], r4.x, b3);
                }
                float sum = (b0 + b1) + (b2 + b3);
                if (g == 0) sum += drcur;
                baseB[it & 1][g][lane] = sum;
                drcur = drnx;
            }
            __syncthreads();
        }
    } else {
        float wregB[33];
        #pragma unroll
        for (int j = 1; j <= 32; j++) wregB[j] = g_w[s * 256 + lane + j];
        float wregU[32];
        #pragma unroll
        for (int k = 0; k < 32; k++) {
            int idx = lane - 31 + k;
            wregU[k] = (idx >= 1) ? g_w[s * 256 + idx] : 0.f;
        }
        float wr[8];
        #pragma unroll
        for (int j = 1; j < 8; j++) wr[j] = g_w[s * 256 + j];

        float spkAll[32];
        #pragma unroll
        for (int k = 0; k < 32; k++) spkAll[k] = 0.f;

        for (int it = 0; it <= NCHUNK; it++) {
            if (it >= 1) {
                int c = it - 1;
                int T = c * 32;
                float v = baseB[c & 1][0][lane] + baseB[c & 1][1][lane];
                float a0 = 0.f, a1 = 0.f, a2 = 0.f, a3 = 0.f;
                #pragma unroll
                for (int q = 0; q < 8; q++) {
                    a0 = fmaf(wregB[32 - 4 * q], spkAll[4 * q],     a0);
                    a1 = fmaf(wregB[31 - 4 * q], spkAll[4 * q + 1], a1);
                    a2 = fmaf(wregB[30 - 4 * q], spkAll[4 * q + 2], a2);
                    a3 = fmaf(wregB[29 - 4 * q], spkAll[4 * q + 3], a3);
                }
                v += (a0 + a1) + (a2 + a3);

                #pragma unroll
                for (int b = 0; b < 4; b++) {
                    float sv[8];
                    #pragma unroll
                    for (int i = 0; i < 8; i++)
                        sv[i] = __shfl_sync(0xffffffffu, v, 8 * b + i);
                    #pragma unroll
                    for (int i = 0; i < 8; i++) {
                        spkAll[8 * b + i] = sv[i] > 0.f ? 1.f : 0.f;
                        #pragma unroll
                        for (int j = i + 1; j < 8; j++)
                            sv[j] = fmaf(spkAll[8 * b + i], wr[j - i], sv[j]);
                    }
                    #pragma unroll
                    for (int i = 0; i < 8; i++)
                        v = fmaf(spkAll[8 * b + i], wregU[31 - 8 * b - i], v);
                }

                float myspk = v > 0.f ? 1.f : 0.f;
                ring[(T + lane) & 255] = myspk;
                oth[T + lane] = v;
                osp[T + lane] = myspk;
            }
            __syncthreads();
        }
    }
}

// ---------------------------------------------------------------------------
// Kernel 4: merged postprocess (exact R10 version).
// grid (157, 2): y=0 -> root conv; y=1, x<79 -> transpose both outputs.
// ---------------------------------------------------------------------------
__global__ void __launch_bounds__(256) post_kernel(float* __restrict__ out) {
    __shared__ __align__(16) char buf[43200];
    int tid = threadIdx.x;

    if (blockIdx.y == 1) {
        if (blockIdx.x >= 79) return;
        float (*sh)[257] = reinterpret_cast<float (*)[257]>(buf);  // [SUB][257]
        int t0 = blockIdx.x * 256;
        #pragma unroll
        for (int half = 0; half < 2; half++) {
            const float* in = half ? g_th_sT : g_spk_sT;
            float* op = out + (half ? OFF_TH : OFF_SPK);
            int t = t0 + tid;
            if (t < T_DATA) {
                #pragma unroll
                for (int s = 0; s < SUB; s++)
                    sh[s][tid] = in[s * T_DATA + t];
            }
            __syncthreads();
            for (int i = tid; i < SUB * 256; i += 256) {
                int tl = i / SUB, s = i % SUB;
                int tt = t0 + tl;
                if (tt < T_DATA) op[tt * SUB + s] = sh[s][tl];
            }
            __syncthreads();
        }
        return;
    }

    float* sK   = reinterpret_cast<float*>(buf);             // 4000
    float* sSpk = reinterpret_cast<float*>(buf) + 4000;      // 20*328 = 6560
    int t0 = blockIdx.x * 128;

    for (int i = tid; i < SUB * T_NO; i += 256) sK[i] = g_K[i];
    for (int i = tid; i < SUB * 327; i += 256) {
        int s = i / 327;
        int m = i % 327;
        int gt = t0 - 200 + m;
        sSpk[s * 328 + m] = (gt >= 0 && gt < T_DATA) ? g_spk_sT[s * T_DATA + gt] : 0.f;
    }
    __syncthreads();

    if (tid >= 128) return;
    int lt = tid;
    int t = t0 + lt;
    if (t >= T_DATA) return;

    float acc0 = 0.f, acc1 = 0.f;
    for (int s = 0; s < SUB; s++) {
        const float* Ks = sK + s * T_NO;
        const float* Ss = sSpk + s * 328 + lt;
        #pragma unroll 4
        for (int u = 0; u < T_NO; u += 2) {
            acc0 = fmaf(Ks[u],     Ss[199 - u], acc0);
            acc1 = fmaf(Ks[u + 1], Ss[198 - u], acc1);
        }
    }
    out[OFF_V + t] = acc0 + acc1;
}

// ---------------------------------------------------------------------------
// Launch
// ---------------------------------------------------------------------------
extern "C" void kernel_launch(void* const* d_in, const int* in_sizes, int n_in,
                              void* d_out, int out_size) {
    const float* S_e    = (const float*)d_in[0];
    const float* S_i    = (const float*)d_in[1];
    const float* Csyn_e = (const float*)d_in[2];
    const float* Csyn_i = (const float*)d_in[3];
    const float* W_conv = (const float*)d_in[4];
    const float* thresh = (const float*)d_in[5];
    const float* W_ff   = (const float*)d_in[6];
    const float* W_ff2  = (const float*)d_in[7];
    const float* Tau    = (const float*)d_in[8];
    const float* W_root = (const float*)d_in[9];
    const float* W_hist = (const float*)d_in[10];
    float* out = (float*)d_out;

    (void)in_sizes; (void)n_in; (void)out_size;

    gemmprep_kernel<<<GEMM_BLOCKS + PREP_BLOCKS, 256>>>(
        S_e, S_i, Csyn_e, Csyn_i, W_conv, W_hist, Tau, W_root, out);
    {
        dim3 grid((T_DATA + 511) / 512, SUB);
        conv_drive_kernel<<<grid, 128>>>(W_ff, W_ff2, thresh);
    }
    scan_kernel<<<SUB, 96>>>();
    {
        dim3 grid(157, 2);
        post_kernel<<<grid, 256>>>(out);
    }
}